// round 16
// baseline (speedup 1.0000x reference)
#include <cuda_runtime.h>
#include <cuda_fp16.h>
#include <math.h>
#include <stdint.h>

// Problem constants
#define BBB 32
#define SSS 512
#define DDD 1024
#define HHH 16
#define DHH 64
#define LLL 4
#define DFFF 2048
#define DMEMM 512
#define TTT (BBB * SSS)   // 16384 tokens

// ---------------------------------------------------------------------------
// Scratch (static device globals)
// ---------------------------------------------------------------------------
__device__ float g_pe[(size_t)SSS * DDD];             //   2 MB
__device__ __half g_tmph[(size_t)TTT * DDD];          //  32 MB residual delta fp16
__device__ __half g_hf[(size_t)TTT * DDD];            //  32 MB residual fp16
__device__ __half g_ff[(size_t)TTT * DFFF];           //  64 MB ctx / ff fp16
__device__ __half g_qkvh[(size_t)TTT * 3 * DDD];      //  96 MB qkv fp16
#define WTOT 34078720ULL
__device__ __half g_wh[WTOT];                         //  68 MB weights fp16

#define OFF_QKV 0ULL
#define OFF_WO  12582912ULL
#define OFF_W1  16777216ULL
#define OFF_W2  25165824ULL
#define OFF_WOUT 33554432ULL

// ---------------------------------------------------------------------------
// PTX helpers (baseline sm_80+)
// ---------------------------------------------------------------------------
__device__ __forceinline__ uint32_t smem_u32(const void* p) {
    uint32_t a;
    asm("{ .reg .u64 t; cvta.to.shared.u64 t, %1; cvt.u32.u64 %0, t; }" : "=r"(a) : "l"(p));
    return a;
}

#define CP16(saddr, gptr) \
    asm volatile("cp.async.cg.shared.global [%0], [%1], 16;" :: "r"(saddr), "l"(gptr))
#define CPCOMMIT() asm volatile("cp.async.commit_group;" ::: "memory")
#define CPWAIT(n)  asm volatile("cp.async.wait_group %0;" :: "n"(n) : "memory")

#define LDSM4(r, addr)                                                          \
    asm volatile("ldmatrix.sync.aligned.m8n8.x4.shared.b16 {%0,%1,%2,%3}, [%4];" \
        : "=r"((r)[0]), "=r"((r)[1]), "=r"((r)[2]), "=r"((r)[3]) : "r"(addr))

#define LDSM4T(r, addr)                                                          \
    asm volatile("ldmatrix.sync.aligned.m8n8.x4.trans.shared.b16 {%0,%1,%2,%3}, [%4];" \
        : "=r"((r)[0]), "=r"((r)[1]), "=r"((r)[2]), "=r"((r)[3]) : "r"(addr))

#define MMA_F16(d, a, b0v, b1v)                                                 \
    asm volatile("mma.sync.aligned.m16n8k16.row.col.f32.f16.f16.f32 "           \
        "{%0,%1,%2,%3}, {%4,%5,%6,%7}, {%8,%9}, {%0,%1,%2,%3};"                 \
        : "+f"((d)[0]), "+f"((d)[1]), "+f"((d)[2]), "+f"((d)[3])                \
        : "r"((a)[0]), "r"((a)[1]), "r"((a)[2]), "r"((a)[3]), "r"(b0v), "r"(b1v))

#define EX2_H2(d, s) asm("ex2.approx.f16x2 %0, %1;" : "=r"(d) : "r"(s))

__device__ __forceinline__ uint32_t pack_h2(float a, float b) {
    uint32_t r;
    asm("cvt.rn.f16x2.f32 %0, %1, %2;" : "=r"(r) : "f"(b), "f"(a));
    return r;
}
__device__ __forceinline__ float2 unpack_h2(uint32_t u) {
    __half2 h = *reinterpret_cast<__half2*>(&u);
    return __half22float2(h);
}

// ---------------------------------------------------------------------------
// 0) merged weight convert (fp16), one launch
// ---------------------------------------------------------------------------
#define F4_QKV 3145728
#define F4_WO  (F4_QKV + 1048576)
#define F4_W1  (F4_WO + 2097152)
#define F4_W2  (F4_W1 + 2097152)
#define F4_ALL (F4_W2 + 131072)

__global__ __launch_bounds__(256)
void cvt_all(const float* __restrict__ Wqkv, const float* __restrict__ Wo,
             const float* __restrict__ W1, const float* __restrict__ W2,
             const float* __restrict__ Wout, __half* __restrict__ hi) {
    int i = blockIdx.x * 256 + threadIdx.x;
    if (i >= F4_ALL) return;
    const float* src;
    int li;
    if (i < F4_QKV)      { src = Wqkv; li = i; }
    else if (i < F4_WO)  { src = Wo;   li = i - F4_QKV; }
    else if (i < F4_W1)  { src = W1;   li = i - F4_WO; }
    else if (i < F4_W2)  { src = W2;   li = i - F4_W1; }
    else                 { src = Wout; li = i - F4_W2; }
    float4 v = reinterpret_cast<const float4*>(src)[li];
    reinterpret_cast<__half2*>(hi)[2 * i] =
        __halves2half2(__float2half_rn(v.x), __float2half_rn(v.y));
    reinterpret_cast<__half2*>(hi)[2 * i + 1] =
        __halves2half2(__float2half_rn(v.z), __float2half_rn(v.w));
}

// ---------------------------------------------------------------------------
// 1a) PE table
// ---------------------------------------------------------------------------
__global__ __launch_bounds__(256)
void pe_table_kernel(float* __restrict__ pe) {
    int idx = blockIdx.x * 256 + threadIdx.x;
    int d = idx & (DDD - 1);
    int s = idx >> 10;
    float div = expf((float)(d & ~1) * (-9.2103403719761836f / (float)DDD));
    float ang = (float)s * div;
    pe[idx] = (d & 1) ? cosf(ang) : sinf(ang);
}

// ---------------------------------------------------------------------------
// 1b) hf[s,b,:] = fp16(x[b,s,:] + PE[s,:])
// ---------------------------------------------------------------------------
__global__ __launch_bounds__(256)
void add_pe_kernel(const float* __restrict__ x, const float* __restrict__ pe,
                   __half* __restrict__ hf) {
    int i4 = blockIdx.x * 256 + threadIdx.x;
    int d4  = i4 & 255;
    int row = i4 >> 8;
    int s   = row >> 5;
    int b   = row & 31;
    float4 xv = reinterpret_cast<const float4*>(x)[((size_t)(b * SSS + s) << 8) + d4];
    float4 pv = reinterpret_cast<const float4*>(pe)[((size_t)s << 8) + d4];
    reinterpret_cast<__half2*>(hf)[2 * i4] =
        __halves2half2(__float2half_rn(xv.x + pv.x), __float2half_rn(xv.y + pv.y));
    reinterpret_cast<__half2*>(hf)[2 * i4 + 1] =
        __halves2half2(__float2half_rn(xv.z + pv.z), __float2half_rn(xv.w + pv.w));
}

// ---------------------------------------------------------------------------
// 2) HMMA GEMM, fp16, BK=64, 3-stage cp.async pipeline.
//    512 threads: 16 warps of 32x32 (32 accs/thread) -> 2 CTAs/SM at <=64 regs,
//    8 warps/SMSP for latency hiding.
//    C = A @ Wh^T + bias.  OUTMODE: 0 = float C, 1 = fp16 Ch.
// ---------------------------------------------------------------------------
#define SROWB 144
#define SEG_B 18432u
#define STG_B 36864u
#define GEMM_SMEM (3 * 36864)

template <int PERM>
__device__ __forceinline__ void load_stage(
    uint32_t sbase, const __half* __restrict__ A, const __half* __restrict__ Wh,
    int m0, int n0, int K, int k0, int t) {
#pragma unroll
    for (int i = 0; i < 4; ++i) {
        int u = t + i * 512;                 // 0..2047
        int sel = u >> 10;                   // 0 A, 1 Wh
        int v = u & 1023;
        int row = v >> 3, seg = v & 7;
        const __half* src;
        if (sel == 0) {
            int garow = m0 + row;
            if (PERM) garow = ((garow & 511) << 5) | (garow >> 9);
            src = A + (size_t)garow * K + k0 + seg * 8;
        } else {
            src = Wh + (size_t)(n0 + row) * K + k0 + seg * 8;
        }
        uint32_t dst = sbase + (uint32_t)sel * SEG_B + (uint32_t)(row * SROWB + seg * 16);
        CP16(dst, src);
    }
}

template <int RELU, int PERM, int OUTMODE>
__global__ __launch_bounds__(512, 2)
void gemm_mma(const __half* __restrict__ A, const __half* __restrict__ Wh,
              const float* __restrict__ bias, float* __restrict__ C,
              __half* __restrict__ Ch,
              int M, int N, int K) {
    extern __shared__ char smem[];
    const uint32_t sb = smem_u32(smem);
    const int t    = threadIdx.x;
    const int lane = t & 31;
    const int w    = t >> 5;       // 0..15
    const int wm   = w & 3;        // 4 m-warps
    const int wn   = w >> 2;       // 4 n-warps
    const int m0   = blockIdx.y * 128;
    const int n0   = blockIdx.x * 128;

    float acc[2][4][4];
#pragma unroll
    for (int a = 0; a < 2; a++)
#pragma unroll
        for (int b = 0; b < 4; b++)
#pragma unroll
            for (int c = 0; c < 4; c++) acc[a][b][c] = 0.f;

    const uint32_t a_off = (uint32_t)((wm * 32 + (lane & 15)) * SROWB + (lane >> 4) * 16);
    const int brow = wn * 32 + (lane & 7) + ((lane & 16) >> 1);
    const uint32_t b_off = (uint32_t)(brow * SROWB + ((lane >> 3) & 1) * 16);

    const int NC = K >> 6;
    load_stage<PERM>(sb, A, Wh, m0, n0, K, 0, t);
    CPCOMMIT();
    if (NC > 1) {
        load_stage<PERM>(sb + STG_B, A, Wh, m0, n0, K, 64, t);
    }
    CPCOMMIT();

    int buf = 0;
    for (int c = 0; c < NC; ++c) {
        CPWAIT(1);
        __syncthreads();
        if (c + 2 < NC) {
            int nb = buf + 2; if (nb >= 3) nb -= 3;
            load_stage<PERM>(sb + (uint32_t)nb * STG_B, A, Wh, m0, n0, K,
                             (c + 2) << 6, t);
        }
        CPCOMMIT();
        const uint32_t stb = sb + (uint32_t)buf * STG_B;
#pragma unroll
        for (int ks = 0; ks < 4; ++ks) {
            const uint32_t ao = stb + a_off + ks * 32;
            const uint32_t bo = stb + SEG_B + b_off + ks * 32;
            uint32_t fb0[4], fb1[4];
            LDSM4(fb0, bo);
            LDSM4(fb1, bo + 16 * SROWB);
#pragma unroll
            for (int mi = 0; mi < 2; ++mi) {
                uint32_t fa[4];
                LDSM4(fa, ao + mi * (16 * SROWB));
                MMA_F16(acc[mi][0], fa, fb0[0], fb0[1]);
                MMA_F16(acc[mi][1], fa, fb0[2], fb0[3]);
                MMA_F16(acc[mi][2], fa, fb1[0], fb1[1]);
                MMA_F16(acc[mi][3], fa, fb1[2], fb1[3]);
            }
        }
        if (++buf == 3) buf = 0;
    }

    const int qrow = lane >> 2;
    const int qcol = (lane & 3) * 2;
#pragma unroll
    for (int mi = 0; mi < 2; ++mi) {
        const int row0 = m0 + wm * 32 + mi * 16 + qrow;
#pragma unroll
        for (int ni = 0; ni < 4; ++ni) {
            const int col = n0 + wn * 32 + ni * 8 + qcol;
            const float bb0 = bias[col];
            const float bb1 = bias[col + 1];
            float v00 = acc[mi][ni][0] + bb0;
            float v01 = acc[mi][ni][1] + bb1;
            float v10 = acc[mi][ni][2] + bb0;
            float v11 = acc[mi][ni][3] + bb1;
            if (RELU) {
                v00 = fmaxf(v00, 0.f); v01 = fmaxf(v01, 0.f);
                v10 = fmaxf(v10, 0.f); v11 = fmaxf(v11, 0.f);
            }
            if (OUTMODE == 0) {
                *reinterpret_cast<float2*>(C + (size_t)row0 * N + col) =
                    make_float2(v00, v01);
                *reinterpret_cast<float2*>(C + (size_t)(row0 + 8) * N + col) =
                    make_float2(v10, v11);
            } else {
                *reinterpret_cast<__half2*>(Ch + (size_t)row0 * N + col) =
                    __halves2half2(__float2half_rn(v00), __float2half_rn(v01));
                *reinterpret_cast<__half2*>(Ch + (size_t)(row0 + 8) * N + col) =
                    __halves2half2(__float2half_rn(v10), __float2half_rn(v11));
            }
        }
    }
}

// ---------------------------------------------------------------------------
// 3) HMMA flash attention, all-fp16 single-pass, base-2 softmax (ex2.f16x2)
// ---------------------------------------------------------------------------
#define AROWB 144
#define AQ_OFF 0u
#define AST0   18432u
#define ASTG   18432u
#define AK_OFF 0u
#define AV_OFF 9216u
#define ATTN_SMEM (18432 + 2 * 18432)
// 0.125 (1/sqrt(64)) * log2(e)
#define C_SCALE 0.18033688011112042f

__device__ __forceinline__ void attn_load_kv(
    uint32_t sbase, const __half* __restrict__ qkv, int b, int hd, int kt, int t) {
#pragma unroll
    for (int i = 0; i < 4; ++i) {
        int u = t + i * 256;
        int sel = u >> 9;                // 0 K, 1 V
        int v = u & 511;
        int row = v >> 3, seg = v & 7;
        int off = sel ? 2048 : 1024;
        const __half* src =
            qkv + ((size_t)((kt * 64 + row) * BBB + b)) * 3072 + off + hd + seg * 8;
        uint32_t dst = sbase + (uint32_t)sel * 9216u + (uint32_t)(row * AROWB + seg * 16);
        CP16(dst, src);
    }
}

__global__ __launch_bounds__(256, 2)
void attn_mma_kernel(const __half* __restrict__ qkv, __half* __restrict__ ctx) {
    extern __shared__ char smem[];
    const uint32_t sb = smem_u32(smem);
    const int t    = threadIdx.x;
    const int lane = t & 31;
    const int w    = t >> 5;
    const int b    = blockIdx.y >> 4;
    const int h    = blockIdx.y & 15;
    const int q0   = blockIdx.x * 128;
    const int hd   = h * DHH;

#pragma unroll
    for (int i = 0; i < 4; ++i) {
        int u = t + i * 256;
        int row = u >> 3, seg = u & 7;
        const __half* src = qkv + ((size_t)((q0 + row) * BBB + b)) * 3072 + hd + seg * 8;
        uint32_t dst = sb + AQ_OFF + (uint32_t)(row * AROWB + seg * 16);
        CP16(dst, src);
    }
    CPCOMMIT();
    attn_load_kv(sb + AST0, qkv, b, hd, 0, t);
    CPCOMMIT();

    float Oa[8][4];
#pragma unroll
    for (int j = 0; j < 8; j++)
#pragma unroll
        for (int c = 0; c < 4; c++) Oa[j][c] = 0.f;
    float m0r = -1e30f, m1r = -1e30f, l0r = 0.f, l1r = 0.f;

    const uint32_t arow_off = (uint32_t)((w * 16 + (lane & 15)) * AROWB + (lane >> 4) * 16);
    const uint32_t brow_off = (uint32_t)(((lane & 7) + ((lane & 16) >> 1)) * AROWB +
                                         ((lane >> 3) & 1) * 16);
    const uint32_t vrow_off = (uint32_t)((lane & 15) * AROWB + (lane >> 4) * 16);

    for (int kt = 0; kt < 8; ++kt) {
        CPWAIT(0);
        __syncthreads();
        if (kt + 1 < 8) {
            attn_load_kv(sb + AST0 + (uint32_t)((kt + 1) & 1) * ASTG, qkv, b, hd,
                         kt + 1, t);
            CPCOMMIT();
        }
        const uint32_t stg = sb + AST0 + (uint32_t)(kt & 1) * ASTG;

        float st[8][4];
#pragma unroll
        for (int j = 0; j < 8; j++)
#pragma unroll
            for (int c = 0; c < 4; c++) st[j][c] = 0.f;
#pragma unroll
        for (int kc = 0; kc < 4; ++kc) {
            uint32_t fa[4];
            LDSM4(fa, sb + AQ_OFF + arow_off + kc * 32);
#pragma unroll
            for (int g = 0; g < 4; ++g) {
                uint32_t fb[4];
                LDSM4(fb, stg + AK_OFF + brow_off + g * (16 * AROWB) + kc * 32);
                MMA_F16(st[2 * g],     fa, fb[0], fb[1]);
                MMA_F16(st[2 * g + 1], fa, fb[2], fb[3]);
            }
        }

        float mx0 = -1e30f, mx1 = -1e30f;
#pragma unroll
        for (int j = 0; j < 8; j++) {
            st[j][0] *= C_SCALE; st[j][1] *= C_SCALE;
            st[j][2] *= C_SCALE; st[j][3] *= C_SCALE;
            mx0 = fmaxf(mx0, fmaxf(st[j][0], st[j][1]));
            mx1 = fmaxf(mx1, fmaxf(st[j][2], st[j][3]));
        }
        mx0 = fmaxf(mx0, __shfl_xor_sync(0xffffffffu, mx0, 1));
        mx0 = fmaxf(mx0, __shfl_xor_sync(0xffffffffu, mx0, 2));
        mx1 = fmaxf(mx1, __shfl_xor_sync(0xffffffffu, mx1, 1));
        mx1 = fmaxf(mx1, __shfl_xor_sync(0xffffffffu, mx1, 2));
        const float nm0 = fmaxf(m0r, mx0), nm1 = fmaxf(m1r, mx1);
        const float al0 = exp2f(m0r - nm0), al1 = exp2f(m1r - nm1);

        uint32_t pp[8][2];
        float s0 = 0.f, s1 = 0.f;
#pragma unroll
        for (int j = 0; j < 8; j++) {
            uint32_t q0p = pack_h2(st[j][0] - nm0, st[j][1] - nm0);
            uint32_t q1p = pack_h2(st[j][2] - nm1, st[j][3] - nm1);
            EX2_H2(pp[j][0], q0p);
            EX2_H2(pp[j][1], q1p);
            float2 v0 = unpack_h2(pp[j][0]);
            float2 v1 = unpack_h2(pp[j][1]);
            s0 += v0.x + v0.y;
            s1 += v1.x + v1.y;
        }
        s0 += __shfl_xor_sync(0xffffffffu, s0, 1);
        s0 += __shfl_xor_sync(0xffffffffu, s0, 2);
        s1 += __shfl_xor_sync(0xffffffffu, s1, 1);
        s1 += __shfl_xor_sync(0xffffffffu, s1, 2);
        l0r = l0r * al0 + s0;
        l1r = l1r * al1 + s1;
        m0r = nm0; m1r = nm1;
#pragma unroll
        for (int j = 0; j < 8; j++) {
            Oa[j][0] *= al0; Oa[j][1] *= al0;
            Oa[j][2] *= al1; Oa[j][3] *= al1;
        }

#pragma unroll
        for (int kc = 0; kc < 4; ++kc) {
            uint32_t ph[4];
            ph[0] = pp[2 * kc][0];
            ph[1] = pp[2 * kc][1];
            ph[2] = pp[2 * kc + 1][0];
            ph[3] = pp[2 * kc + 1][1];
            const uint32_t vbase = stg + AV_OFF + (uint32_t)(kc * 16 * AROWB) + vrow_off;
#pragma unroll
            for (int g = 0; g < 4; ++g) {
                uint32_t fv[4];
                LDSM4T(fv, vbase + g * 32);
                MMA_F16(Oa[2 * g],     ph, fv[0], fv[1]);
                MMA_F16(Oa[2 * g + 1], ph, fv[2], fv[3]);
            }
        }
    }

    const float inv0 = 1.f / l0r;
    const float inv1 = 1.f / l1r;
    const int r_lo = q0 + w * 16 + (lane >> 2);
    const int col0 = hd + (lane & 3) * 2;
#pragma unroll
    for (int j = 0; j < 8; j++) {
        const int col = col0 + j * 8;
        size_t o0 = ((size_t)(r_lo * BBB + b)) * 1024 + col;
        size_t o1 = ((size_t)((r_lo + 8) * BBB + b)) * 1024 + col;
        *reinterpret_cast<__half2*>(ctx + o0) =
            __halves2half2(__float2half_rn(Oa[j][0] * inv0),
                           __float2half_rn(Oa[j][1] * inv0));
        *reinterpret_cast<__half2*>(ctx + o1) =
            __halves2half2(__float2half_rn(Oa[j][2] * inv1),
                           __float2half_rn(Oa[j][3] * inv1));
    }
}

// ---------------------------------------------------------------------------
// 4) LayerNorm, fp16 in/out, fp32 math: out = LN(a + r) * g + b
// ---------------------------------------------------------------------------
__global__ __launch_bounds__(256)
void ln_kernel(const __half* __restrict__ a, const __half* __restrict__ r,
               const float* __restrict__ g, const float* __restrict__ b,
               __half* __restrict__ out) {
    __shared__ float red1[8];
    __shared__ float red2[8];
    const int t = threadIdx.x;
    const int lane = t & 31;
    const int w = t >> 5;
    const size_t row = blockIdx.x;
    __half2 a0 = reinterpret_cast<const __half2*>(a + row * 1024)[2 * t];
    __half2 a1 = reinterpret_cast<const __half2*>(a + row * 1024)[2 * t + 1];
    float2 f0 = __half22float2(a0);
    float2 f1 = __half22float2(a1);
    float4 v = make_float4(f0.x, f0.y, f1.x, f1.y);
    if (r != nullptr) {
        __half2 r0 = reinterpret_cast<const __half2*>(r + row * 1024)[2 * t];
        __half2 r1 = reinterpret_cast<const __half2*>(r + row * 1024)[2 * t + 1];
        float2 g0 = __half22float2(r0);
        float2 g1 = __half22float2(r1);
        v.x += g0.x; v.y += g0.y; v.z += g1.x; v.w += g1.y;
    }
    float s = v.x + v.y + v.z + v.w;
#pragma unroll
    for (int o = 16; o > 0; o >>= 1) s += __shfl_xor_sync(0xffffffffu, s, o);
    if (lane == 0) red1[w] = s;
    __syncthreads();
    float mu = (red1[0] + red1[1] + red1[2] + red1[3] +
                red1[4] + red1[5] + red1[6] + red1[7]) * (1.f / 1024.f);
    float dx = v.x - mu, dy = v.y - mu, dz = v.z - mu, dw = v.w - mu;
    float q = dx * dx + dy * dy + dz * dz + dw * dw;
#pragma unroll
    for (int o = 16; o > 0; o >>= 1) q += __shfl_xor_sync(0xffffffffu, q, o);
    if (lane == 0) red2[w] = q;
    __syncthreads();
    float var = (red2[0] + red2[1] + red2[2] + red2[3] +
                 red2[4] + red2[5] + red2[6] + red2[7]) * (1.f / 1024.f);
    float inv = rsqrtf(var + 1e-5f);
    float4 g4 = reinterpret_cast<const float4*>(g)[t];
    float4 b4 = reinterpret_cast<const float4*>(b)[t];
    float o0 = dx * inv * g4.x + b4.x;
    float o1 = dy * inv * g4.y + b4.y;
    float o2 = dz * inv * g4.z + b4.z;
    float o3 = dw * inv * g4.w + b4.w;
    reinterpret_cast<__half2*>(out + row * 1024)[2 * t] =
        __halves2half2(__float2half_rn(o0), __float2half_rn(o1));
    reinterpret_cast<__half2*>(out + row * 1024)[2 * t + 1] =
        __halves2half2(__float2half_rn(o2), __float2half_rn(o3));
}

// ---------------------------------------------------------------------------
// Host orchestration
// ---------------------------------------------------------------------------
extern "C" void kernel_launch(void* const* d_in, const int* in_sizes, int n_in,
                              void* d_out, int out_size) {
    (void)in_sizes; (void)n_in; (void)out_size;
    const float* x    = (const float*)d_in[0];
    const float* Wqkv = (const float*)d_in[1];
    const float* bqkv = (const float*)d_in[2];
    const float* Wo   = (const float*)d_in[3];
    const float* bo   = (const float*)d_in[4];
    const float* W1   = (const float*)d_in[5];
    const float* b1   = (const float*)d_in[6];
    const float* W2   = (const float*)d_in[7];
    const float* b2   = (const float*)d_in[8];
    const float* ln1g = (const float*)d_in[9];
    const float* ln1b = (const float*)d_in[10];
    const float* ln2g = (const float*)d_in[11];
    const float* ln2b = (const float*)d_in[12];
    const float* lnfg = (const float*)d_in[13];
    const float* lnfb = (const float*)d_in[14];
    const float* Wout = (const float*)d_in[15];
    const float* bout = (const float*)d_in[16];
    float* out = (float*)d_out;

    float *pe;
    __half *hf, *ff, *qvh, *wh, *tmph;
    cudaGetSymbolAddress((void**)&pe,   g_pe);
    cudaGetSymbolAddress((void**)&tmph, g_tmph);
    cudaGetSymbolAddress((void**)&hf,   g_hf);
    cudaGetSymbolAddress((void**)&ff,   g_ff);
    cudaGetSymbolAddress((void**)&qvh,  g_qkvh);
    cudaGetSymbolAddress((void**)&wh,   g_wh);

    cudaFuncSetAttribute(gemm_mma<0, 0, 1>, cudaFuncAttributeMaxDynamicSharedMemorySize, GEMM_SMEM);
    cudaFuncSetAttribute(gemm_mma<1, 0, 1>, cudaFuncAttributeMaxDynamicSharedMemorySize, GEMM_SMEM);
    cudaFuncSetAttribute(gemm_mma<0, 1, 0>, cudaFuncAttributeMaxDynamicSharedMemorySize, GEMM_SMEM);
    cudaFuncSetAttribute(attn_mma_kernel, cudaFuncAttributeMaxDynamicSharedMemorySize, ATTN_SMEM);

    cvt_all<<<(F4_ALL + 255) / 256, 256>>>(Wqkv, Wo, W1, W2, Wout, wh);
    pe_table_kernel<<<(SSS * DDD) / 256, 256>>>(pe);
    add_pe_kernel<<<(TTT * DDD / 4) / 256, 256>>>(x, pe, hf);

    for (int l = 0; l < LLL; l++) {
        const __half* wq_h = wh + OFF_QKV + (size_t)l * 3145728;
        const __half* wo_h = wh + OFF_WO + (size_t)l * 1048576;
        const __half* w1_h = wh + OFF_W1 + (size_t)l * 2097152;
        const __half* w2_h = wh + OFF_W2 + (size_t)l * 2097152;

        // qkv (fp16) = hf @ Wqkv^T + bqkv
        gemm_mma<0, 0, 1><<<dim3(3072 / 128, TTT / 128), 512, GEMM_SMEM>>>(
            hf, wq_h, bqkv + (size_t)l * 3072, nullptr, qvh, TTT, 3072, 1024);
        // ctx (fp16) = flash attention
        attn_mma_kernel<<<dim3(SSS / 128, BBB * HHH), 256, ATTN_SMEM>>>(qvh, ff);
        // tmph (fp16) = ctx @ Wo^T + bo
        gemm_mma<0, 0, 1><<<dim3(1024 / 128, TTT / 128), 512, GEMM_SMEM>>>(
            ff, wo_h, bo + (size_t)l * 1024, nullptr, tmph, TTT, 1024, 1024);
        // hf = LN(hf + tmph)
        ln_kernel<<<TTT, 256>>>(hf, tmph, ln1g + (size_t)l * 1024,
                                ln1b + (size_t)l * 1024, hf);
        // ff (fp16) = relu(hf @ W1^T + b1)
        gemm_mma<1, 0, 1><<<dim3(2048 / 128, TTT / 128), 512, GEMM_SMEM>>>(
            hf, w1_h, b1 + (size_t)l * 2048, nullptr, ff, TTT, 2048, 1024);
        // tmph (fp16) = ff @ W2^T + b2
        gemm_mma<0, 0, 1><<<dim3(1024 / 128, TTT / 128), 512, GEMM_SMEM>>>(
            ff, w2_h, b2 + (size_t)l * 1024, nullptr, tmph, TTT, 1024, 2048);
        // hf = LN(hf + tmph)
        ln_kernel<<<TTT, 256>>>(hf, tmph, ln2g + (size_t)l * 1024,
                                ln2b + (size_t)l * 1024, hf);
    }

    // final norm
    ln_kernel<<<TTT, 256>>>(hf, nullptr, lnfg, lnfb, hf);
    // out = hf_final @ Wout^T + bout   [fp32 out, fused transpose]
    gemm_mma<0, 1, 0><<<dim3(DMEMM / 128, TTT / 128), 512, GEMM_SMEM>>>(
        hf, wh + OFF_WOUT, bout, out, nullptr, TTT, DMEMM, 1024);
}

// round 17
// speedup vs baseline: 1.0474x; 1.0474x over previous
#include <cuda_runtime.h>
#include <cuda_fp16.h>
#include <math.h>
#include <stdint.h>

// Problem constants
#define BBB 32
#define SSS 512
#define DDD 1024
#define HHH 16
#define DHH 64
#define LLL 4
#define DFFF 2048
#define DMEMM 512
#define TTT (BBB * SSS)   // 16384 tokens

// ---------------------------------------------------------------------------
// Scratch (static device globals)
// ---------------------------------------------------------------------------
__device__ __half g_tmph[(size_t)TTT * DDD];          //  32 MB residual delta fp16
__device__ __half g_hf[(size_t)TTT * DDD];            //  32 MB residual fp16
__device__ __half g_ff[(size_t)TTT * DFFF];           //  64 MB ctx / ff fp16
__device__ __half g_qkvh[(size_t)TTT * 3 * DDD];      //  96 MB qkv fp16
#define WTOT 34078720ULL
__device__ __half g_wh[WTOT];                         //  68 MB weights fp16

#define OFF_QKV 0ULL
#define OFF_WO  12582912ULL
#define OFF_W1  16777216ULL
#define OFF_W2  25165824ULL
#define OFF_WOUT 33554432ULL

// ---------------------------------------------------------------------------
// PTX helpers (baseline sm_80+)
// ---------------------------------------------------------------------------
__device__ __forceinline__ uint32_t smem_u32(const void* p) {
    uint32_t a;
    asm("{ .reg .u64 t; cvta.to.shared.u64 t, %1; cvt.u32.u64 %0, t; }" : "=r"(a) : "l"(p));
    return a;
}

#define CP16(saddr, gptr) \
    asm volatile("cp.async.cg.shared.global [%0], [%1], 16;" :: "r"(saddr), "l"(gptr))
#define CPCOMMIT() asm volatile("cp.async.commit_group;" ::: "memory")
#define CPWAIT(n)  asm volatile("cp.async.wait_group %0;" :: "n"(n) : "memory")

#define LDSM4(r, addr)                                                          \
    asm volatile("ldmatrix.sync.aligned.m8n8.x4.shared.b16 {%0,%1,%2,%3}, [%4];" \
        : "=r"((r)[0]), "=r"((r)[1]), "=r"((r)[2]), "=r"((r)[3]) : "r"(addr))

#define LDSM4T(r, addr)                                                          \
    asm volatile("ldmatrix.sync.aligned.m8n8.x4.trans.shared.b16 {%0,%1,%2,%3}, [%4];" \
        : "=r"((r)[0]), "=r"((r)[1]), "=r"((r)[2]), "=r"((r)[3]) : "r"(addr))

#define MMA_F16(d, a, b0v, b1v)                                                 \
    asm volatile("mma.sync.aligned.m16n8k16.row.col.f32.f16.f16.f32 "           \
        "{%0,%1,%2,%3}, {%4,%5,%6,%7}, {%8,%9}, {%0,%1,%2,%3};"                 \
        : "+f"((d)[0]), "+f"((d)[1]), "+f"((d)[2]), "+f"((d)[3])                \
        : "r"((a)[0]), "r"((a)[1]), "r"((a)[2]), "r"((a)[3]), "r"(b0v), "r"(b1v))

#define EX2_H2(d, s) asm("ex2.approx.f16x2 %0, %1;" : "=r"(d) : "r"(s))

__device__ __forceinline__ uint32_t pack_h2(float a, float b) {
    uint32_t r;
    asm("cvt.rn.f16x2.f32 %0, %1, %2;" : "=r"(r) : "f"(b), "f"(a));
    return r;
}
__device__ __forceinline__ float2 unpack_h2(uint32_t u) {
    __half2 h = *reinterpret_cast<__half2*>(&u);
    return __half22float2(h);
}

// ---------------------------------------------------------------------------
// 0) merged weight convert (fp16), one launch
// ---------------------------------------------------------------------------
#define F4_QKV 3145728
#define F4_WO  (F4_QKV + 1048576)
#define F4_W1  (F4_WO + 2097152)
#define F4_W2  (F4_W1 + 2097152)
#define F4_ALL (F4_W2 + 131072)

__global__ __launch_bounds__(256)
void cvt_all(const float* __restrict__ Wqkv, const float* __restrict__ Wo,
             const float* __restrict__ W1, const float* __restrict__ W2,
             const float* __restrict__ Wout, __half* __restrict__ hi) {
    int i = blockIdx.x * 256 + threadIdx.x;
    if (i >= F4_ALL) return;
    const float* src;
    int li;
    if (i < F4_QKV)      { src = Wqkv; li = i; }
    else if (i < F4_WO)  { src = Wo;   li = i - F4_QKV; }
    else if (i < F4_W1)  { src = W1;   li = i - F4_WO; }
    else if (i < F4_W2)  { src = W2;   li = i - F4_W1; }
    else                 { src = Wout; li = i - F4_W2; }
    float4 v = reinterpret_cast<const float4*>(src)[li];
    reinterpret_cast<__half2*>(hi)[2 * i] =
        __halves2half2(__float2half_rn(v.x), __float2half_rn(v.y));
    reinterpret_cast<__half2*>(hi)[2 * i + 1] =
        __halves2half2(__float2half_rn(v.z), __float2half_rn(v.w));
}

// ---------------------------------------------------------------------------
// 1) Fused PE + transpose: block = one sequence position s.
//    PE[s,:] computed once into smem, applied to all 32 batch rows.
//    hf[s,b,:] = fp16(x[b,s,:] + PE[s,:])
// ---------------------------------------------------------------------------
__global__ __launch_bounds__(256)
void add_pe_kernel(const float* __restrict__ x, __half* __restrict__ hf) {
    __shared__ float pes[DDD];
    const int t = threadIdx.x;
    const int s = blockIdx.x;
#pragma unroll
    for (int j = 0; j < 4; ++j) {
        int d = t * 4 + j;
        float div = expf((float)(d & ~1) * (-9.2103403719761836f / (float)DDD));
        float ang = (float)s * div;
        pes[d] = (d & 1) ? cosf(ang) : sinf(ang);
    }
    __syncthreads();
    float4 pv = reinterpret_cast<const float4*>(pes)[t];
    for (int b = 0; b < BBB; ++b) {
        float4 xv = reinterpret_cast<const float4*>(x)[((size_t)(b * SSS + s) << 8) + t];
        size_t o = ((size_t)(s * BBB + b) << 8) + t;
        reinterpret_cast<__half2*>(hf)[2 * o] =
            __halves2half2(__float2half_rn(xv.x + pv.x), __float2half_rn(xv.y + pv.y));
        reinterpret_cast<__half2*>(hf)[2 * o + 1] =
            __halves2half2(__float2half_rn(xv.z + pv.z), __float2half_rn(xv.w + pv.w));
    }
}

// ---------------------------------------------------------------------------
// 2) HMMA GEMM, fp16, BK=64, 3-stage cp.async pipeline (round-14 config:
//    256 threads, warp tile 64x32 — the measured Pareto point).
//    C = A @ Wh^T + bias.  OUTMODE: 0 = float C, 1 = fp16 Ch.
// ---------------------------------------------------------------------------
#define SROWB 144
#define SEG_B 18432u
#define STG_B 36864u
#define GEMM_SMEM (3 * 36864)

template <int PERM>
__device__ __forceinline__ void load_stage(
    uint32_t sbase, const __half* __restrict__ A, const __half* __restrict__ Wh,
    int m0, int n0, int K, int k0, int t) {
#pragma unroll
    for (int i = 0; i < 8; ++i) {
        int u = t + i * 256;
        int sel = u >> 10;                   // 0 A, 1 Wh
        int v = u & 1023;
        int row = v >> 3, seg = v & 7;
        const __half* src;
        if (sel == 0) {
            int garow = m0 + row;
            if (PERM) garow = ((garow & 511) << 5) | (garow >> 9);
            src = A + (size_t)garow * K + k0 + seg * 8;
        } else {
            src = Wh + (size_t)(n0 + row) * K + k0 + seg * 8;
        }
        uint32_t dst = sbase + (uint32_t)sel * SEG_B + (uint32_t)(row * SROWB + seg * 16);
        CP16(dst, src);
    }
}

template <int RELU, int PERM, int OUTMODE>
__global__ __launch_bounds__(256, 2)
void gemm_mma(const __half* __restrict__ A, const __half* __restrict__ Wh,
              const float* __restrict__ bias, float* __restrict__ C,
              __half* __restrict__ Ch,
              int M, int N, int K) {
    extern __shared__ char smem[];
    const uint32_t sb = smem_u32(smem);
    const int t    = threadIdx.x;
    const int lane = t & 31;
    const int w    = t >> 5;
    const int wm   = w & 1;
    const int wn   = w >> 1;
    const int m0   = blockIdx.y * 128;
    const int n0   = blockIdx.x * 128;

    float acc[4][4][4];
#pragma unroll
    for (int a = 0; a < 4; a++)
#pragma unroll
        for (int b = 0; b < 4; b++)
#pragma unroll
            for (int c = 0; c < 4; c++) acc[a][b][c] = 0.f;

    const uint32_t a_off = (uint32_t)((wm * 64 + (lane & 15)) * SROWB + (lane >> 4) * 16);
    const int brow = wn * 32 + (lane & 7) + ((lane & 16) >> 1);
    const uint32_t b_off = (uint32_t)(brow * SROWB + ((lane >> 3) & 1) * 16);

    const int NC = K >> 6;
    load_stage<PERM>(sb, A, Wh, m0, n0, K, 0, t);
    CPCOMMIT();
    if (NC > 1) {
        load_stage<PERM>(sb + STG_B, A, Wh, m0, n0, K, 64, t);
    }
    CPCOMMIT();

    int buf = 0;
    for (int c = 0; c < NC; ++c) {
        CPWAIT(1);
        __syncthreads();
        if (c + 2 < NC) {
            int nb = buf + 2; if (nb >= 3) nb -= 3;
            load_stage<PERM>(sb + (uint32_t)nb * STG_B, A, Wh, m0, n0, K,
                             (c + 2) << 6, t);
        }
        CPCOMMIT();
        const uint32_t stb = sb + (uint32_t)buf * STG_B;
#pragma unroll
        for (int ks = 0; ks < 4; ++ks) {
            const uint32_t ao = stb + a_off + ks * 32;
            const uint32_t bo = stb + SEG_B + b_off + ks * 32;
            uint32_t fb0[4], fb1[4];
            LDSM4(fb0, bo);
            LDSM4(fb1, bo + 16 * SROWB);
#pragma unroll
            for (int mi = 0; mi < 4; ++mi) {
                uint32_t fa[4];
                LDSM4(fa, ao + mi * (16 * SROWB));
                MMA_F16(acc[mi][0], fa, fb0[0], fb0[1]);
                MMA_F16(acc[mi][1], fa, fb0[2], fb0[3]);
                MMA_F16(acc[mi][2], fa, fb1[0], fb1[1]);
                MMA_F16(acc[mi][3], fa, fb1[2], fb1[3]);
            }
        }
        if (++buf == 3) buf = 0;
    }

    const int qrow = lane >> 2;
    const int qcol = (lane & 3) * 2;
#pragma unroll
    for (int mi = 0; mi < 4; ++mi) {
        const int row0 = m0 + wm * 64 + mi * 16 + qrow;
#pragma unroll
        for (int ni = 0; ni < 4; ++ni) {
            const int col = n0 + wn * 32 + ni * 8 + qcol;
            const float bb0 = bias[col];
            const float bb1 = bias[col + 1];
            float v00 = acc[mi][ni][0] + bb0;
            float v01 = acc[mi][ni][1] + bb1;
            float v10 = acc[mi][ni][2] + bb0;
            float v11 = acc[mi][ni][3] + bb1;
            if (RELU) {
                v00 = fmaxf(v00, 0.f); v01 = fmaxf(v01, 0.f);
                v10 = fmaxf(v10, 0.f); v11 = fmaxf(v11, 0.f);
            }
            if (OUTMODE == 0) {
                *reinterpret_cast<float2*>(C + (size_t)row0 * N + col) =
                    make_float2(v00, v01);
                *reinterpret_cast<float2*>(C + (size_t)(row0 + 8) * N + col) =
                    make_float2(v10, v11);
            } else {
                *reinterpret_cast<__half2*>(Ch + (size_t)row0 * N + col) =
                    __halves2half2(__float2half_rn(v00), __float2half_rn(v01));
                *reinterpret_cast<__half2*>(Ch + (size_t)(row0 + 8) * N + col) =
                    __halves2half2(__float2half_rn(v10), __float2half_rn(v11));
            }
        }
    }
}

// ---------------------------------------------------------------------------
// 3) HMMA flash attention, all-fp16 single-pass, base-2 softmax (ex2.f16x2)
// ---------------------------------------------------------------------------
#define AROWB 144
#define AQ_OFF 0u
#define AST0   18432u
#define ASTG   18432u
#define AK_OFF 0u
#define AV_OFF 9216u
#define ATTN_SMEM (18432 + 2 * 18432)
// 0.125 (1/sqrt(64)) * log2(e)
#define C_SCALE 0.18033688011112042f

__device__ __forceinline__ void attn_load_kv(
    uint32_t sbase, const __half* __restrict__ qkv, int b, int hd, int kt, int t) {
#pragma unroll
    for (int i = 0; i < 4; ++i) {
        int u = t + i * 256;
        int sel = u >> 9;                // 0 K, 1 V
        int v = u & 511;
        int row = v >> 3, seg = v & 7;
        int off = sel ? 2048 : 1024;
        const __half* src =
            qkv + ((size_t)((kt * 64 + row) * BBB + b)) * 3072 + off + hd + seg * 8;
        uint32_t dst = sbase + (uint32_t)sel * 9216u + (uint32_t)(row * AROWB + seg * 16);
        CP16(dst, src);
    }
}

__global__ __launch_bounds__(256, 2)
void attn_mma_kernel(const __half* __restrict__ qkv, __half* __restrict__ ctx) {
    extern __shared__ char smem[];
    const uint32_t sb = smem_u32(smem);
    const int t    = threadIdx.x;
    const int lane = t & 31;
    const int w    = t >> 5;
    const int b    = blockIdx.y >> 4;
    const int h    = blockIdx.y & 15;
    const int q0   = blockIdx.x * 128;
    const int hd   = h * DHH;

#pragma unroll
    for (int i = 0; i < 4; ++i) {
        int u = t + i * 256;
        int row = u >> 3, seg = u & 7;
        const __half* src = qkv + ((size_t)((q0 + row) * BBB + b)) * 3072 + hd + seg * 8;
        uint32_t dst = sb + AQ_OFF + (uint32_t)(row * AROWB + seg * 16);
        CP16(dst, src);
    }
    CPCOMMIT();
    attn_load_kv(sb + AST0, qkv, b, hd, 0, t);
    CPCOMMIT();

    float Oa[8][4];
#pragma unroll
    for (int j = 0; j < 8; j++)
#pragma unroll
        for (int c = 0; c < 4; c++) Oa[j][c] = 0.f;
    float m0r = -1e30f, m1r = -1e30f, l0r = 0.f, l1r = 0.f;

    const uint32_t arow_off = (uint32_t)((w * 16 + (lane & 15)) * AROWB + (lane >> 4) * 16);
    const uint32_t brow_off = (uint32_t)(((lane & 7) + ((lane & 16) >> 1)) * AROWB +
                                         ((lane >> 3) & 1) * 16);
    const uint32_t vrow_off = (uint32_t)((lane & 15) * AROWB + (lane >> 4) * 16);

    for (int kt = 0; kt < 8; ++kt) {
        CPWAIT(0);
        __syncthreads();
        if (kt + 1 < 8) {
            attn_load_kv(sb + AST0 + (uint32_t)((kt + 1) & 1) * ASTG, qkv, b, hd,
                         kt + 1, t);
            CPCOMMIT();
        }
        const uint32_t stg = sb + AST0 + (uint32_t)(kt & 1) * ASTG;

        float st[8][4];
#pragma unroll
        for (int j = 0; j < 8; j++)
#pragma unroll
            for (int c = 0; c < 4; c++) st[j][c] = 0.f;
#pragma unroll
        for (int kc = 0; kc < 4; ++kc) {
            uint32_t fa[4];
            LDSM4(fa, sb + AQ_OFF + arow_off + kc * 32);
#pragma unroll
            for (int g = 0; g < 4; ++g) {
                uint32_t fb[4];
                LDSM4(fb, stg + AK_OFF + brow_off + g * (16 * AROWB) + kc * 32);
                MMA_F16(st[2 * g],     fa, fb[0], fb[1]);
                MMA_F16(st[2 * g + 1], fa, fb[2], fb[3]);
            }
        }

        float mx0 = -1e30f, mx1 = -1e30f;
#pragma unroll
        for (int j = 0; j < 8; j++) {
            st[j][0] *= C_SCALE; st[j][1] *= C_SCALE;
            st[j][2] *= C_SCALE; st[j][3] *= C_SCALE;
            mx0 = fmaxf(mx0, fmaxf(st[j][0], st[j][1]));
            mx1 = fmaxf(mx1, fmaxf(st[j][2], st[j][3]));
        }
        mx0 = fmaxf(mx0, __shfl_xor_sync(0xffffffffu, mx0, 1));
        mx0 = fmaxf(mx0, __shfl_xor_sync(0xffffffffu, mx0, 2));
        mx1 = fmaxf(mx1, __shfl_xor_sync(0xffffffffu, mx1, 1));
        mx1 = fmaxf(mx1, __shfl_xor_sync(0xffffffffu, mx1, 2));
        const float nm0 = fmaxf(m0r, mx0), nm1 = fmaxf(m1r, mx1);
        const float al0 = exp2f(m0r - nm0), al1 = exp2f(m1r - nm1);

        uint32_t pp[8][2];
        float s0 = 0.f, s1 = 0.f;
#pragma unroll
        for (int j = 0; j < 8; j++) {
            uint32_t q0p = pack_h2(st[j][0] - nm0, st[j][1] - nm0);
            uint32_t q1p = pack_h2(st[j][2] - nm1, st[j][3] - nm1);
            EX2_H2(pp[j][0], q0p);
            EX2_H2(pp[j][1], q1p);
            float2 v0 = unpack_h2(pp[j][0]);
            float2 v1 = unpack_h2(pp[j][1]);
            s0 += v0.x + v0.y;
            s1 += v1.x + v1.y;
        }
        s0 += __shfl_xor_sync(0xffffffffu, s0, 1);
        s0 += __shfl_xor_sync(0xffffffffu, s0, 2);
        s1 += __shfl_xor_sync(0xffffffffu, s1, 1);
        s1 += __shfl_xor_sync(0xffffffffu, s1, 2);
        l0r = l0r * al0 + s0;
        l1r = l1r * al1 + s1;
        m0r = nm0; m1r = nm1;
#pragma unroll
        for (int j = 0; j < 8; j++) {
            Oa[j][0] *= al0; Oa[j][1] *= al0;
            Oa[j][2] *= al1; Oa[j][3] *= al1;
        }

#pragma unroll
        for (int kc = 0; kc < 4; ++kc) {
            uint32_t ph[4];
            ph[0] = pp[2 * kc][0];
            ph[1] = pp[2 * kc][1];
            ph[2] = pp[2 * kc + 1][0];
            ph[3] = pp[2 * kc + 1][1];
            const uint32_t vbase = stg + AV_OFF + (uint32_t)(kc * 16 * AROWB) + vrow_off;
#pragma unroll
            for (int g = 0; g < 4; ++g) {
                uint32_t fv[4];
                LDSM4T(fv, vbase + g * 32);
                MMA_F16(Oa[2 * g],     ph, fv[0], fv[1]);
                MMA_F16(Oa[2 * g + 1], ph, fv[2], fv[3]);
            }
        }
    }

    const float inv0 = 1.f / l0r;
    const float inv1 = 1.f / l1r;
    const int r_lo = q0 + w * 16 + (lane >> 2);
    const int col0 = hd + (lane & 3) * 2;
#pragma unroll
    for (int j = 0; j < 8; j++) {
        const int col = col0 + j * 8;
        size_t o0 = ((size_t)(r_lo * BBB + b)) * 1024 + col;
        size_t o1 = ((size_t)((r_lo + 8) * BBB + b)) * 1024 + col;
        *reinterpret_cast<__half2*>(ctx + o0) =
            __halves2half2(__float2half_rn(Oa[j][0] * inv0),
                           __float2half_rn(Oa[j][1] * inv0));
        *reinterpret_cast<__half2*>(ctx + o1) =
            __halves2half2(__float2half_rn(Oa[j][2] * inv1),
                           __float2half_rn(Oa[j][3] * inv1));
    }
}

// ---------------------------------------------------------------------------
// 4) LayerNorm, fp16 in/out, fp32 math: out = LN(a + r) * g + b
// ---------------------------------------------------------------------------
__global__ __launch_bounds__(256)
void ln_kernel(const __half* __restrict__ a, const __half* __restrict__ r,
               const float* __restrict__ g, const float* __restrict__ b,
               __half* __restrict__ out) {
    __shared__ float red1[8];
    __shared__ float red2[8];
    const int t = threadIdx.x;
    const int lane = t & 31;
    const int w = t >> 5;
    const size_t row = blockIdx.x;
    __half2 a0 = reinterpret_cast<const __half2*>(a + row * 1024)[2 * t];
    __half2 a1 = reinterpret_cast<const __half2*>(a + row * 1024)[2 * t + 1];
    float2 f0 = __half22float2(a0);
    float2 f1 = __half22float2(a1);
    float4 v = make_float4(f0.x, f0.y, f1.x, f1.y);
    if (r != nullptr) {
        __half2 r0 = reinterpret_cast<const __half2*>(r + row * 1024)[2 * t];
        __half2 r1 = reinterpret_cast<const __half2*>(r + row * 1024)[2 * t + 1];
        float2 g0 = __half22float2(r0);
        float2 g1 = __half22float2(r1);
        v.x += g0.x; v.y += g0.y; v.z += g1.x; v.w += g1.y;
    }
    float s = v.x + v.y + v.z + v.w;
#pragma unroll
    for (int o = 16; o > 0; o >>= 1) s += __shfl_xor_sync(0xffffffffu, s, o);
    if (lane == 0) red1[w] = s;
    __syncthreads();
    float mu = (red1[0] + red1[1] + red1[2] + red1[3] +
                red1[4] + red1[5] + red1[6] + red1[7]) * (1.f / 1024.f);
    float dx = v.x - mu, dy = v.y - mu, dz = v.z - mu, dw = v.w - mu;
    float q = dx * dx + dy * dy + dz * dz + dw * dw;
#pragma unroll
    for (int o = 16; o > 0; o >>= 1) q += __shfl_xor_sync(0xffffffffu, q, o);
    if (lane == 0) red2[w] = q;
    __syncthreads();
    float var = (red2[0] + red2[1] + red2[2] + red2[3] +
                 red2[4] + red2[5] + red2[6] + red2[7]) * (1.f / 1024.f);
    float inv = rsqrtf(var + 1e-5f);
    float4 g4 = reinterpret_cast<const float4*>(g)[t];
    float4 b4 = reinterpret_cast<const float4*>(b)[t];
    float o0 = dx * inv * g4.x + b4.x;
    float o1 = dy * inv * g4.y + b4.y;
    float o2 = dz * inv * g4.z + b4.z;
    float o3 = dw * inv * g4.w + b4.w;
    reinterpret_cast<__half2*>(out + row * 1024)[2 * t] =
        __halves2half2(__float2half_rn(o0), __float2half_rn(o1));
    reinterpret_cast<__half2*>(out + row * 1024)[2 * t + 1] =
        __halves2half2(__float2half_rn(o2), __float2half_rn(o3));
}

// ---------------------------------------------------------------------------
// Host orchestration
// ---------------------------------------------------------------------------
extern "C" void kernel_launch(void* const* d_in, const int* in_sizes, int n_in,
                              void* d_out, int out_size) {
    (void)in_sizes; (void)n_in; (void)out_size;
    const float* x    = (const float*)d_in[0];
    const float* Wqkv = (const float*)d_in[1];
    const float* bqkv = (const float*)d_in[2];
    const float* Wo   = (const float*)d_in[3];
    const float* bo   = (const float*)d_in[4];
    const float* W1   = (const float*)d_in[5];
    const float* b1   = (const float*)d_in[6];
    const float* W2   = (const float*)d_in[7];
    const float* b2   = (const float*)d_in[8];
    const float* ln1g = (const float*)d_in[9];
    const float* ln1b = (const float*)d_in[10];
    const float* ln2g = (const float*)d_in[11];
    const float* ln2b = (const float*)d_in[12];
    const float* lnfg = (const float*)d_in[13];
    const float* lnfb = (const float*)d_in[14];
    const float* Wout = (const float*)d_in[15];
    const float* bout = (const float*)d_in[16];
    float* out = (float*)d_out;

    __half *hf, *ff, *qvh, *wh, *tmph;
    cudaGetSymbolAddress((void**)&tmph, g_tmph);
    cudaGetSymbolAddress((void**)&hf,   g_hf);
    cudaGetSymbolAddress((void**)&ff,   g_ff);
    cudaGetSymbolAddress((void**)&qvh,  g_qkvh);
    cudaGetSymbolAddress((void**)&wh,   g_wh);

    cudaFuncSetAttribute(gemm_mma<0, 0, 1>, cudaFuncAttributeMaxDynamicSharedMemorySize, GEMM_SMEM);
    cudaFuncSetAttribute(gemm_mma<1, 0, 1>, cudaFuncAttributeMaxDynamicSharedMemorySize, GEMM_SMEM);
    cudaFuncSetAttribute(gemm_mma<0, 1, 0>, cudaFuncAttributeMaxDynamicSharedMemorySize, GEMM_SMEM);
    cudaFuncSetAttribute(attn_mma_kernel, cudaFuncAttributeMaxDynamicSharedMemorySize, ATTN_SMEM);

    cvt_all<<<(F4_ALL + 255) / 256, 256>>>(Wqkv, Wo, W1, W2, Wout, wh);
    add_pe_kernel<<<SSS, 256>>>(x, hf);

    for (int l = 0; l < LLL; l++) {
        const __half* wq_h = wh + OFF_QKV + (size_t)l * 3145728;
        const __half* wo_h = wh + OFF_WO + (size_t)l * 1048576;
        const __half* w1_h = wh + OFF_W1 + (size_t)l * 2097152;
        const __half* w2_h = wh + OFF_W2 + (size_t)l * 2097152;

        // qkv (fp16) = hf @ Wqkv^T + bqkv
        gemm_mma<0, 0, 1><<<dim3(3072 / 128, TTT / 128), 256, GEMM_SMEM>>>(
            hf, wq_h, bqkv + (size_t)l * 3072, nullptr, qvh, TTT, 3072, 1024);
        // ctx (fp16) = flash attention
        attn_mma_kernel<<<dim3(SSS / 128, BBB * HHH), 256, ATTN_SMEM>>>(qvh, ff);
        // tmph (fp16) = ctx @ Wo^T + bo
        gemm_mma<0, 0, 1><<<dim3(1024 / 128, TTT / 128), 256, GEMM_SMEM>>>(
            ff, wo_h, bo + (size_t)l * 1024, nullptr, tmph, TTT, 1024, 1024);
        // hf = LN(hf + tmph)
        ln_kernel<<<TTT, 256>>>(hf, tmph, ln1g + (size_t)l * 1024,
                                ln1b + (size_t)l * 1024, hf);
        // ff (fp16) = relu(hf @ W1^T + b1)
        gemm_mma<1, 0, 1><<<dim3(2048 / 128, TTT / 128), 256, GEMM_SMEM>>>(
            hf, w1_h, b1 + (size_t)l * 2048, nullptr, ff, TTT, 2048, 1024);
        // tmph (fp16) = ff @ W2^T + b2
        gemm_mma<0, 0, 1><<<dim3(1024 / 128, TTT / 128), 256, GEMM_SMEM>>>(
            ff, w2_h, b2 + (size_t)l * 1024, nullptr, tmph, TTT, 1024, 2048);
        // hf = LN(hf + tmph)
        ln_kernel<<<TTT, 256>>>(hf, tmph, ln2g + (size_t)l * 1024,
                                ln2b + (size_t)l * 1024, hf);
    }

    // final norm
    ln_kernel<<<TTT, 256>>>(hf, nullptr, lnfg, lnfb, hf);
    // out = hf_final @ Wout^T + bout   [fp32 out, fused transpose]
    gemm_mma<0, 1, 0><<<dim3(DMEMM / 128, TTT / 128), 256, GEMM_SMEM>>>(
        hf, wh + OFF_WOUT, bout, out, nullptr, TTT, DMEMM, 1024);
}